// round 1
// baseline (speedup 1.0000x reference)
#include <cuda_runtime.h>
#include <math.h>

// Problem geometry (fixed by the dataset): B=8, C=3, H=W=512, TILE=128, STRIDE=64
// Cell decomposition: 8x8 cells of 64x64 per image; tile (ty,tx), ty,tx in [0,7),
// covers cells {ty,ty+1} x {tx,tx+1}.
#define BSZ   8
#define NCH   3
#define HH    512
#define WW    512
#define PLANE (HH*WW)          // 262144
#define NCELL 8
#define NTILE 7
#define INV_TILE_ELEMS (1.0f/49152.0f)   // 1/(C*128*128)

// Scratch for per-(b,cell) sums. Written fresh every launch (no accumulation),
// so kernel_launch stays deterministic and graph-capturable.
__device__ float g_cellsum[BSZ * NCELL * NCELL];

// ---------------------------------------------------------------------------
// Kernel 1: per-(b, cy, cx) 64x64 cell sum of (img_c0+img_c1+img_c2) * mask.
// One block per cell: 512 blocks x 256 threads. float4 loads.
// ---------------------------------------------------------------------------
__global__ void __launch_bounds__(256) cell_sum_kernel(
    const float* __restrict__ img, const float* __restrict__ mask)
{
    const int cx = blockIdx.x, cy = blockIdx.y, b = blockIdx.z;
    const int tid = threadIdx.x;

    const float* mb = mask + (b * HH + cy * 64) * WW + cx * 64;
    const float* ib = img + ((b * NCH) * HH + cy * 64) * WW + cx * 64;

    float acc = 0.0f;
    // 64 rows x 16 float4/row = 1024 float4 -> 4 per thread
    #pragma unroll
    for (int k = 0; k < 4; k++) {
        int f   = tid + k * 256;          // 0..1023
        int row = f >> 4;
        int col = (f & 15) << 2;
        int off = row * WW + col;
        float4 m  = *(const float4*)(mb + off);
        float4 i0 = *(const float4*)(ib + off);
        float4 i1 = *(const float4*)(ib + PLANE + off);
        float4 i2 = *(const float4*)(ib + 2 * PLANE + off);
        acc += (i0.x + i1.x + i2.x) * m.x
             + (i0.y + i1.y + i2.y) * m.y
             + (i0.z + i1.z + i2.z) * m.z
             + (i0.w + i1.w + i2.w) * m.w;
    }

    // block reduction: warp shuffle, then lane-0s via shared
    #pragma unroll
    for (int o = 16; o > 0; o >>= 1)
        acc += __shfl_xor_sync(0xffffffffu, acc, o);

    __shared__ float swarp[8];
    if ((tid & 31) == 0) swarp[tid >> 5] = acc;
    __syncthreads();
    if (tid == 0) {
        float v = swarp[0];
        #pragma unroll
        for (int w = 1; w < 8; w++) v += swarp[w];
        g_cellsum[(b * NCELL + cy) * NCELL + cx] = v;
    }
}

// ---------------------------------------------------------------------------
// Kernel 2: build 49 tile logits per batch in shared, then per pixel:
//   lsum  = sum of logits of covering tiles  (<=2 x <=2 neighborhood)
//   local = lsum / counts * mask       (counts = nty*ntx in {1,2,4}, exact)
//   out   = sigmoid(0.5*g + 0.5*local) * mask
// Grid: (256 blocks of 1024 px, B). float4 in/out.
// ---------------------------------------------------------------------------
__global__ void __launch_bounds__(256) final_kernel(
    const float* __restrict__ mask, const float* __restrict__ gmap,
    float* __restrict__ out)
{
    __shared__ float cs[NCELL * NCELL];
    __shared__ float lg[NTILE * NTILE];

    const int tid = threadIdx.x;
    const int b   = blockIdx.y;

    if (tid < NCELL * NCELL) cs[tid] = g_cellsum[b * NCELL * NCELL + tid];
    __syncthreads();
    if (tid < NTILE * NTILE) {
        int ty = tid / NTILE, tx = tid % NTILE;
        lg[tid] = (cs[ty * NCELL + tx]       + cs[ty * NCELL + tx + 1] +
                   cs[(ty + 1) * NCELL + tx] + cs[(ty + 1) * NCELL + tx + 1])
                  * INV_TILE_ELEMS;
    }
    __syncthreads();

    const int idx = (blockIdx.x * 256 + tid) * 4;   // 0..PLANE-1, float4-aligned
    const int y   = idx >> 9;                       // /512
    const int xb  = idx & 511;                      // x of lane 0; x..x+3 share the
                                                    // same 64-cell (xb % 4 == 0)
    const int cy  = y >> 6;
    const int cx  = xb >> 6;
    const int ty0 = max(cy - 1, 0), ty1 = min(cy, NTILE - 1);
    const int tx0 = max(cx - 1, 0), tx1 = min(cx, NTILE - 1);

    float lsum = 0.0f;
    for (int ty = ty0; ty <= ty1; ty++)
        for (int tx = tx0; tx <= tx1; tx++)
            lsum += lg[ty * NTILE + tx];
    const float cnt  = (float)((ty1 - ty0 + 1) * (tx1 - tx0 + 1));
    const float lavg = lsum * (1.0f / cnt);          // cnt in {1,2,4}: exact rcp

    const int boff = b * PLANE + idx;
    const float4 m4 = *(const float4*)(mask + boff);
    const float4 g4 = *(const float4*)(gmap + boff);

    float4 o4;
    {
        const float* mp = &m4.x;
        const float* gp = &g4.x;
        float*       op = &o4.x;
        #pragma unroll
        for (int e = 0; e < 4; e++) {
            float local = lavg * mp[e];
            float z     = 0.5f * gp[e] + 0.5f * local;
            op[e]       = mp[e] / (1.0f + __expf(-z));
        }
    }
    *(float4*)(out + boff) = o4;
}

// ---------------------------------------------------------------------------
// Inputs (metadata order):
//  0 image          (8,3,512,512) f32
//  1 valid_mask     (8,1,512,512) f32
//  2 global_heatmap (8,1,512,512) f32
//  3 tile_mask_bank (49,1,512,512) f32   (unused: structure is analytic)
//  4 tile_mask_counts (1,512,512) f32    (unused: counts = nty*ntx exactly)
//  5 row_idx (7,128) i32, 6 col_idx (7,128) i32  (unused: fixed geometry)
// ---------------------------------------------------------------------------
extern "C" void kernel_launch(void* const* d_in, const int* in_sizes, int n_in,
                              void* d_out, int out_size)
{
    const float* image = (const float*)d_in[0];
    const float* mask  = (const float*)d_in[1];
    const float* gmap  = (const float*)d_in[2];
    float*       out   = (float*)d_out;

    cell_sum_kernel<<<dim3(NCELL, NCELL, BSZ), 256>>>(image, mask);
    final_kernel<<<dim3(PLANE / 1024, BSZ), 256>>>(mask, gmap, out);
}

// round 2
// speedup vs baseline: 1.3821x; 1.3821x over previous
#include <cuda_runtime.h>
#include <math.h>

// Problem geometry (fixed): B=8, C=3, H=W=512, TILE=128, STRIDE=64
// Cell decomposition: 8x8 cells of 64x64 per image; tile (ty,tx) covers
// cells {ty,ty+1} x {tx,tx+1}.
#define BSZ   8
#define NCH   3
#define HH    512
#define WW    512
#define PLANE (HH*WW)          // 262144
#define NCELL 8
#define NTILE 7
#define INV_TILE_ELEMS (1.0f/49152.0f)   // 1/(C*128*128)

__device__ float g_cellsum[BSZ * NCELL * NCELL];

__device__ __forceinline__ float tanh_approx(float x) {
    float y;
    asm("tanh.approx.f32 %0, %1;" : "=f"(y) : "f"(x));
    return y;
}

// ---------------------------------------------------------------------------
// Kernel 1: per-(b, cy, cx) 64x64 cell sum of (img_c0+img_c1+img_c2) * mask.
// 512 blocks x 256 threads, float4 loads. Measured at the LTS cap (~6.7TB/s).
// ---------------------------------------------------------------------------
__global__ void __launch_bounds__(256) cell_sum_kernel(
    const float* __restrict__ img, const float* __restrict__ mask)
{
    const int cx = blockIdx.x, cy = blockIdx.y, b = blockIdx.z;
    const int tid = threadIdx.x;

    const float* mb = mask + (b * HH + cy * 64) * WW + cx * 64;
    const float* ib = img + ((b * NCH) * HH + cy * 64) * WW + cx * 64;

    float acc = 0.0f;
    #pragma unroll
    for (int k = 0; k < 4; k++) {
        int f   = tid + k * 256;          // 0..1023 float4 slots
        int row = f >> 4;
        int col = (f & 15) << 2;
        int off = row * WW + col;
        float4 m  = *(const float4*)(mb + off);
        float4 i0 = *(const float4*)(ib + off);
        float4 i1 = *(const float4*)(ib + PLANE + off);
        float4 i2 = *(const float4*)(ib + 2 * PLANE + off);
        acc += (i0.x + i1.x + i2.x) * m.x
             + (i0.y + i1.y + i2.y) * m.y
             + (i0.z + i1.z + i2.z) * m.z
             + (i0.w + i1.w + i2.w) * m.w;
    }

    #pragma unroll
    for (int o = 16; o > 0; o >>= 1)
        acc += __shfl_xor_sync(0xffffffffu, acc, o);

    __shared__ float swarp[8];
    if ((tid & 31) == 0) swarp[tid >> 5] = acc;
    __syncthreads();
    if (tid == 0) {
        float v = swarp[0];
        #pragma unroll
        for (int w = 1; w < 8; w++) v += swarp[w];
        g_cellsum[(b * NCELL + cy) * NCELL + cx] = v;
    }
}

// ---------------------------------------------------------------------------
// Kernel 2: 49 tile logits in shared, then per pixel:
//   lavg = (sum of covering tile logits) / (nty*ntx)     [counts exact]
//   out  = m * (0.5*tanh(0.25*(g + lavg*m)) + 0.5)       [= sigmoid(...)*m]
// 1 MUFU + ~4 FMA per pixel. IPT=4 float4 per thread, 512 blocks.
// ---------------------------------------------------------------------------
#define FK_IPT 4                      // float4s per thread
#define FK_TPB 256
#define FK_PX_PER_BLOCK (FK_TPB * FK_IPT * 4)   // 4096 pixels

__global__ void __launch_bounds__(FK_TPB) final_kernel(
    const float* __restrict__ mask, const float* __restrict__ gmap,
    float* __restrict__ out)
{
    __shared__ float cs[NCELL * NCELL];
    __shared__ float lg[NTILE * NTILE];
    __shared__ float lavg_cell[NCELL * NCELL];   // per-cell averaged logit

    const int tid = threadIdx.x;
    const int b   = blockIdx.y;

    if (tid < NCELL * NCELL) cs[tid] = g_cellsum[b * NCELL * NCELL + tid];
    __syncthreads();
    if (tid < NTILE * NTILE) {
        int ty = tid / NTILE, tx = tid % NTILE;
        lg[tid] = (cs[ty * NCELL + tx]       + cs[ty * NCELL + tx + 1] +
                   cs[(ty + 1) * NCELL + tx] + cs[(ty + 1) * NCELL + tx + 1])
                  * INV_TILE_ELEMS;
    }
    __syncthreads();
    if (tid < NCELL * NCELL) {
        int cy = tid >> 3, cx = tid & 7;
        int ty0 = max(cy - 1, 0), ty1 = min(cy, NTILE - 1);
        int tx0 = max(cx - 1, 0), tx1 = min(cx, NTILE - 1);
        float s = 0.0f;
        for (int ty = ty0; ty <= ty1; ty++)
            for (int tx = tx0; tx <= tx1; tx++)
                s += lg[ty * NTILE + tx];
        lavg_cell[tid] = s * (1.0f / (float)((ty1 - ty0 + 1) * (tx1 - tx0 + 1)));
    }
    __syncthreads();

    const int base = blockIdx.x * FK_PX_PER_BLOCK;   // pixel base in plane
    const int boff = b * PLANE + base;

    float4 m4[FK_IPT], g4[FK_IPT];
    float  la[FK_IPT];
    #pragma unroll
    for (int k = 0; k < FK_IPT; k++) {
        int idx = base + (tid + k * FK_TPB) * 4;   // float4-aligned pixel index
        m4[k] = *(const float4*)(mask + b * PLANE + idx);
        g4[k] = *(const float4*)(gmap + b * PLANE + idx);
        int cy = idx >> 15;                        // (idx/512)/64
        int cx = (idx & 511) >> 6;                 // 4 px share one 64-cell
        la[k] = lavg_cell[cy * NCELL + cx];
    }

    #pragma unroll
    for (int k = 0; k < FK_IPT; k++) {
        int idx = base + (tid + k * FK_TPB) * 4;
        float4 o4;
        o4.x = m4[k].x * (0.5f * tanh_approx(0.25f * (g4[k].x + la[k] * m4[k].x)) + 0.5f);
        o4.y = m4[k].y * (0.5f * tanh_approx(0.25f * (g4[k].y + la[k] * m4[k].y)) + 0.5f);
        o4.z = m4[k].z * (0.5f * tanh_approx(0.25f * (g4[k].z + la[k] * m4[k].z)) + 0.5f);
        o4.w = m4[k].w * (0.5f * tanh_approx(0.25f * (g4[k].w + la[k] * m4[k].w)) + 0.5f);
        *(float4*)(out + b * PLANE + idx) = o4;
    }
}

// ---------------------------------------------------------------------------
// Inputs (metadata order):
//  0 image (8,3,512,512) f32 | 1 valid_mask (8,1,512,512) f32
//  2 global_heatmap (8,1,512,512) f32 | 3 tile_mask_bank (unused)
//  4 tile_mask_counts (unused) | 5 row_idx (unused) | 6 col_idx (unused)
// ---------------------------------------------------------------------------
extern "C" void kernel_launch(void* const* d_in, const int* in_sizes, int n_in,
                              void* d_out, int out_size)
{
    const float* image = (const float*)d_in[0];
    const float* mask  = (const float*)d_in[1];
    const float* gmap  = (const float*)d_in[2];
    float*       out   = (float*)d_out;

    cell_sum_kernel<<<dim3(NCELL, NCELL, BSZ), 256>>>(image, mask);
    final_kernel<<<dim3(PLANE / FK_PX_PER_BLOCK, BSZ), FK_TPB>>>(mask, gmap, out);
}